// round 16
// baseline (speedup 1.0000x reference)
#include <cuda_runtime.h>
#include <cuda_fp16.h>

namespace {

constexpr int TPB = 256;
constexpr int DIM = 2048;
constexpr int S = 4;
constexpr int NC = 6;               // 5 alpha columns + 1 beta column
constexpr int NPK = 14;             // 2 packed sumsq + 12 packed dot partials
constexpr int L = 2048;
constexpr int NW = TPB / 32;        // 8 warps
constexpr int NGROUPS = 4 * 2048;   // 8192
constexpr int PGRID = 152 * 4;      // persistent grid (GB300: 152 SMs x 4 CTAs)
constexpr long long SSTRIDE = (long long)L * DIM;   // stride between streams s

// Packed per-thread weight tiles: g_wp[j][t*4 + k] holds the folded weights
// (norm_weight*fn) for main-kernel thread t's dims {t*4..t*4+3, 1024+t*4..+3}
// as 4 half2. One LDG.128 per column per thread in the main kernel.
__device__ __half2 g_wp[NC][DIM];

// Latency-floor prep: ONE thread per output half2 (6*2048 = 12288 threads).
__global__ void prep_kernel(const float* __restrict__ norm_weight,
                            const float* __restrict__ alpha_fn,
                            const float* __restrict__ beta_fn)
{
    const int idx = blockIdx.x * blockDim.x + threadIdx.x;
    if (idx < NC * DIM) {
        const int jj = idx >> 11;        // 0..5 (5 == beta column)
        const int m = idx & (DIM - 1);   // output slot within column
        const int t = m >> 2;            // main-kernel thread tile
        const int k = m & 3;             // which of the 4 half2

        const int da = (k < 2) ? (t * 4 + 2 * k) : (1024 + t * 4 + 2 * (k - 2));
        const int db = da + 1;

        const float w0 = norm_weight[da];
        const float w1 = norm_weight[db];
        float f0, f1;
        if (jj < 5) { f0 = alpha_fn[da * 5 + jj]; f1 = alpha_fn[db * 5 + jj]; }
        else        { f0 = beta_fn[da];           f1 = beta_fn[db]; }

        g_wp[jj][m] = __floats2half2_rn(w0 * f0, w1 * f1);
    }
    asm volatile("griddepcontrol.launch_dependents;");
}

__device__ __forceinline__ unsigned h2u(__half2 h) { return *reinterpret_cast<unsigned*>(&h); }
__device__ __forceinline__ __half2 u2h(unsigned u) { return *reinterpret_cast<__half2*>(&u); }
__device__ __forceinline__ float unpack_sel(unsigned u, int sel) {
    __half2 h = u2h(u);
    return sel ? __high2float(h) : __low2float(h);
}

__device__ __forceinline__ void cpasync16(void* smem_dst, const void* gmem_src) {
    unsigned saddr = (unsigned)__cvta_generic_to_shared(smem_dst);
    asm volatile("cp.async.cg.shared.global [%0], [%1], 16;" :: "r"(saddr), "l"(gmem_src));
}

__global__ __launch_bounds__(TPB, 4) void hyper_kernel(
    const float* __restrict__ residuals,
    const float* __restrict__ static_alpha,   // [4][5]
    const float* __restrict__ static_beta,    // [4][1]
    const float* __restrict__ alpha_scale_p,  // scalar
    const float* __restrict__ beta_scale_p,   // scalar
    float* __restrict__ out)
{
    const int tid = threadIdx.x;
    const int d0 = tid * 4;
    const int d1 = 1024 + tid * 4;

    // x staging buffer: xbuf[s][c][tid] — lanes contiguous (conflict-free LDS.128).
    // Each thread touches ONLY its own 8 slots -> no cross-thread hazards, so a
    // single buffer works: this iteration's LDS completes (data in regs) long
    // before the next group's cp.async data arrives to overwrite the slot.
    __shared__ float4 xbuf[S][2][TPB];
    __shared__ unsigned red[NW][4][NPK];
    __shared__ float coef[S * 5 + S];  // alpha[4][5] then beta[4]

    const int lane = tid & 31;
    const int wrp = tid >> 5;

    int g = blockIdx.x;
    long long base;
    {
        const int b = g >> 11, l = g & (L - 1);
        base = ((long long)(b * S) * L + l) * DIM;
        #pragma unroll
        for (int s = 0; s < S; s++) {
            const float* p = residuals + base + (long long)s * SSTRIDE;
            cpasync16(&xbuf[s][0][tid], p + d0);
            cpasync16(&xbuf[s][1][tid], p + d1);
        }
        asm volatile("cp.async.commit_group;");
    }

    // PDL: prep's g_wp writes must be visible before any weight load below.
    // The prologue cp.async above (residuals only) overlaps prep's tail.
    asm volatile("griddepcontrol.wait;" ::: "memory");

    while (g < NGROUPS) {
        const int gn = g + PGRID;

        // ---- Wait for this group's staged x, convert to fp16x2 registers.
        asm volatile("cp.async.wait_group 0;" ::: "memory");
        __half2 xh[S][4];
        #pragma unroll
        for (int s = 0; s < S; s++) {
            float4 v0 = xbuf[s][0][tid];
            float4 v1 = xbuf[s][1][tid];
            xh[s][0] = __floats2half2_rn(v0.x, v0.y);
            xh[s][1] = __floats2half2_rn(v0.z, v0.w);
            xh[s][2] = __floats2half2_rn(v1.x, v1.y);
            xh[s][3] = __floats2half2_rn(v1.z, v1.w);
        }

        // ---- Prefetch next group into the same slots (arrives during the
        //      reduction/mix below, keeping DRAM busy through the barriers).
        long long nbase = 0;
        if (gn < NGROUPS) {
            const int nb = gn >> 11, nl = gn & (L - 1);
            nbase = ((long long)(nb * S) * L + nl) * DIM;
            #pragma unroll
            for (int s = 0; s < S; s++) {
                const float* p = residuals + nbase + (long long)s * SSTRIDE;
                cpasync16(&xbuf[s][0][tid], p + d0);
                cpasync16(&xbuf[s][1][tid], p + d1);
            }
        }
        asm volatile("cp.async.commit_group;");

        // ---- Phase 1 entirely in HFMA2 (precision: feeds tanh * 0.01 only).
        unsigned pk[NPK];
        {
            __half ssh[S];
            #pragma unroll
            for (int s = 0; s < S; s++) {
                __half2 a = __hmul2(xh[s][0], xh[s][0]);
                #pragma unroll
                for (int k = 1; k < 4; k++) a = __hfma2(xh[s][k], xh[s][k], a);
                ssh[s] = __hadd(__low2half(a), __high2half(a));
            }
            pk[0] = h2u(__halves2half2(ssh[0], ssh[1]));
            pk[1] = h2u(__halves2half2(ssh[2], ssh[3]));
        }

        #pragma unroll
        for (int j = 0; j < NC; j++) {
            float4 wraw = *reinterpret_cast<const float4*>(&g_wp[j][tid * 4]);
            const __half2* wc = reinterpret_cast<const __half2*>(&wraw);
            __half dh[S];
            #pragma unroll
            for (int s = 0; s < S; s++) {
                __half2 a = __hmul2(xh[s][0], wc[0]);
                #pragma unroll
                for (int k = 1; k < 4; k++) a = __hfma2(xh[s][k], wc[k], a);
                dh[s] = __hadd(__low2half(a), __high2half(a));
            }
            pk[2 + j * 2 + 0] = h2u(__halves2half2(dh[0], dh[1]));
            pk[2 + j * 2 + 1] = h2u(__halves2half2(dh[2], dh[3]));
        }

        // ---- Packed 3-stage butterfly (offsets 16,8,4); lanes 0..3 write smem.
        #pragma unroll
        for (int v = 0; v < NPK; v++) {
            __half2 t = u2h(pk[v]);
            #pragma unroll
            for (int o = 16; o >= 4; o >>= 1)
                t = __hadd2(t, u2h(__shfl_xor_sync(0xffffffffu, h2u(t), o)));
            if (lane < 4) red[wrp][lane][v] = h2u(t);
        }
        __syncthreads();

        // ---- 24 finisher threads: fp32 sum of 32 packed rows + scalar math.
        if (tid < S * NC) {
            const int s = tid / NC;
            const int j = tid % NC;
            const int pss = s >> 1, sel = s & 1;
            const int pdd = 2 + j * 2 + (s >> 1);
            float ss = 0.f, dd = 0.f;
            #pragma unroll
            for (int w = 0; w < NW; w++) {
                #pragma unroll
                for (int ln = 0; ln < 4; ln++) {
                    ss += unpack_sel(red[w][ln][pss], sel);
                    dd += unpack_sel(red[w][ln][pdd], sel);
                }
            }
            const float inv = rsqrtf(ss * (1.0f / DIM) + 1.1920929e-7f);
            const float gv = tanhf(dd * inv);
            if (j < 5) coef[s * 5 + j] = fmaf(gv, *alpha_scale_p, static_alpha[s * 5 + j]);
            else       coef[20 + s]    = fmaf(gv, *beta_scale_p,  static_beta[s]);
        }
        __syncthreads();

        // ---- Mix in fp32 from fp16 x: out_t = sum_s gamma[t][s] * x_s,
        //      gamma[t][s] = alpha[s][t+1] + beta[t] * alpha[s][0].
        float xf[S][8];
        #pragma unroll
        for (int s = 0; s < S; s++) {
            #pragma unroll
            for (int k = 0; k < 4; k++) {
                float2 p = __half22float2(xh[s][k]);
                xf[s][2 * k]     = p.x;
                xf[s][2 * k + 1] = p.y;
            }
        }
        #pragma unroll
        for (int t = 0; t < S; t++) {
            const float bt = coef[20 + t];
            float gam[S];
            #pragma unroll
            for (int s = 0; s < S; s++) gam[s] = fmaf(bt, coef[s * 5], coef[s * 5 + t + 1]);
            float o[8];
            #pragma unroll
            for (int e = 0; e < 8; e++) {
                float r = gam[0] * xf[0][e];
                #pragma unroll
                for (int s = 1; s < S; s++) r = fmaf(gam[s], xf[s][e], r);
                o[e] = r;
            }
            float* po = out + base + (long long)t * SSTRIDE;
            __stcs(reinterpret_cast<float4*>(po + d0), make_float4(o[0], o[1], o[2], o[3]));
            __stcs(reinterpret_cast<float4*>(po + d1), make_float4(o[4], o[5], o[6], o[7]));
        }

        g = gn;
        base = nbase;
    }
}

}  // namespace

extern "C" void kernel_launch(void* const* d_in, const int* in_sizes, int n_in,
                              void* d_out, int out_size) {
    const float* residuals    = (const float*)d_in[0];
    const float* norm_weight  = (const float*)d_in[1];
    const float* static_alpha = (const float*)d_in[2];
    const float* static_beta  = (const float*)d_in[3];
    const float* alpha_fn     = (const float*)d_in[4];
    const float* alpha_scale  = (const float*)d_in[5];
    const float* beta_fn      = (const float*)d_in[6];
    const float* beta_scale   = (const float*)d_in[7];
    float* out = (float*)d_out;

    prep_kernel<<<(NC * DIM + 255) / 256, 256>>>(norm_weight, alpha_fn, beta_fn);

    // PDL launch: hyper begins launching while prep drains; the in-kernel
    // griddepcontrol.wait (after the prologue cp.async) provides ordering.
    cudaLaunchConfig_t cfg = {};
    cfg.gridDim = dim3(PGRID);
    cfg.blockDim = dim3(TPB);
    cfg.dynamicSmemBytes = 0;
    cfg.stream = 0;
    cudaLaunchAttribute attrs[1];
    attrs[0].id = cudaLaunchAttributeProgrammaticStreamSerialization;
    attrs[0].val.programmaticStreamSerializationAllowed = 1;
    cfg.attrs = attrs;
    cfg.numAttrs = 1;
    cudaLaunchKernelEx(&cfg, hyper_kernel, residuals, static_alpha, static_beta,
                       alpha_scale, beta_scale, out);
}

// round 17
// speedup vs baseline: 1.2247x; 1.2247x over previous
#include <cuda_runtime.h>
#include <cuda_fp16.h>

namespace {

constexpr int TPB = 256;
constexpr int DIM = 2048;
constexpr int S = 4;
constexpr int NC = 6;               // 5 alpha columns + 1 beta column
constexpr int NPK = 14;             // 2 packed sumsq + 12 packed dot partials
constexpr int L = 2048;
constexpr int NW = TPB / 32;        // 8 warps
constexpr long long SSTRIDE = (long long)L * DIM;   // stride between streams s

// Packed per-thread weight tiles: g_wp[j][t*4 + k] holds the folded weights
// (norm_weight*fn) for main-kernel thread t's dims {t*4..t*4+3, 1024+t*4..+3}
// as 4 half2. One LDG.128 per column per thread in the main kernel.
__device__ __half2 g_wp[NC][DIM];

// Latency-floor prep: ONE thread per output half2 (6*2048 = 12288 threads).
__global__ void prep_kernel(const float* __restrict__ norm_weight,
                            const float* __restrict__ alpha_fn,
                            const float* __restrict__ beta_fn)
{
    const int idx = blockIdx.x * blockDim.x + threadIdx.x;
    if (idx < NC * DIM) {
        const int jj = idx >> 11;        // 0..5 (5 == beta column)
        const int m = idx & (DIM - 1);   // output slot within column
        const int t = m >> 2;            // main-kernel thread tile
        const int k = m & 3;             // which of the 4 half2

        const int da = (k < 2) ? (t * 4 + 2 * k) : (1024 + t * 4 + 2 * (k - 2));
        const int db = da + 1;

        const float w0 = norm_weight[da];
        const float w1 = norm_weight[db];
        float f0, f1;
        if (jj < 5) { f0 = alpha_fn[da * 5 + jj]; f1 = alpha_fn[db * 5 + jj]; }
        else        { f0 = beta_fn[da];           f1 = beta_fn[db]; }

        g_wp[jj][m] = __floats2half2_rn(w0 * f0, w1 * f1);
    }
    asm volatile("griddepcontrol.launch_dependents;");
}

__device__ __forceinline__ unsigned h2u(__half2 h) { return *reinterpret_cast<unsigned*>(&h); }
__device__ __forceinline__ __half2 u2h(unsigned u) { return *reinterpret_cast<__half2*>(&u); }
__device__ __forceinline__ float unpack_sel(unsigned u, int sel) {
    __half2 h = u2h(u);
    return sel ? __high2float(h) : __low2float(h);
}

__global__ __launch_bounds__(TPB, 4) void hyper_kernel(
    const float* __restrict__ residuals,
    const float* __restrict__ static_alpha,   // [4][5]
    const float* __restrict__ static_beta,    // [4][1]
    const float* __restrict__ alpha_scale_p,  // scalar
    const float* __restrict__ beta_scale_p,   // scalar
    float* __restrict__ out)
{
    const int tid = threadIdx.x;
    const int g = blockIdx.x;          // b * L + l
    const int b = g >> 11;
    const int l = g & (L - 1);
    const long long base = ((long long)(b * S) * L + l) * DIM;

    const int d0 = tid * 4;
    const int d1 = 1024 + tid * 4;

    // ---- Front-batched loads (8 independent LDG.128) — independent of g_wp,
    //      so they overlap the tail of prep_kernel under PDL.
    float4 f[2 * S];
    #pragma unroll
    for (int s = 0; s < S; s++) {
        const float* p = residuals + base + (long long)s * SSTRIDE;
        f[2 * s]     = __ldcs(reinterpret_cast<const float4*>(p + d0));
        f[2 * s + 1] = __ldcs(reinterpret_cast<const float4*>(p + d1));
    }
    __half2 xh[S][4];
    #pragma unroll
    for (int s = 0; s < S; s++) {
        xh[s][0] = __floats2half2_rn(f[2 * s].x,     f[2 * s].y);
        xh[s][1] = __floats2half2_rn(f[2 * s].z,     f[2 * s].w);
        xh[s][2] = __floats2half2_rn(f[2 * s + 1].x, f[2 * s + 1].y);
        xh[s][3] = __floats2half2_rn(f[2 * s + 1].z, f[2 * s + 1].w);
    }

    // ---- Phase 1 entirely in HFMA2 (precision: feeds tanh * 0.01 only).
    unsigned pk[NPK];
    {
        __half ssh[S];
        #pragma unroll
        for (int s = 0; s < S; s++) {
            __half2 a = __hmul2(xh[s][0], xh[s][0]);
            #pragma unroll
            for (int k = 1; k < 4; k++) a = __hfma2(xh[s][k], xh[s][k], a);
            ssh[s] = __hadd(__low2half(a), __high2half(a));
        }
        pk[0] = h2u(__halves2half2(ssh[0], ssh[1]));
        pk[1] = h2u(__halves2half2(ssh[2], ssh[3]));
    }

    // ---- PDL: make prep's g_wp writes visible before the weight loads below.
    asm volatile("griddepcontrol.wait;" ::: "memory");

    #pragma unroll
    for (int j = 0; j < NC; j++) {
        // One LDG.128: 4 half2 of packed folded weights for this thread.
        float4 wraw = *reinterpret_cast<const float4*>(&g_wp[j][tid * 4]);
        const __half2* wc = reinterpret_cast<const __half2*>(&wraw);
        __half dh[S];
        #pragma unroll
        for (int s = 0; s < S; s++) {
            __half2 a = __hmul2(xh[s][0], wc[0]);
            #pragma unroll
            for (int k = 1; k < 4; k++) a = __hfma2(xh[s][k], wc[k], a);
            dh[s] = __hadd(__low2half(a), __high2half(a));
        }
        pk[2 + j * 2 + 0] = h2u(__halves2half2(dh[0], dh[1]));
        pk[2 + j * 2 + 1] = h2u(__halves2half2(dh[2], dh[3]));
    }

    // ---- Packed 4-stage butterfly (offsets 16,8,4,2); lanes 0..1 write smem.
    __shared__ unsigned red[NW][2][NPK];
    __shared__ float coef[S * 5 + S];  // alpha[4][5] then beta[4]
    const int lane = tid & 31;
    const int wrp = tid >> 5;
    #pragma unroll
    for (int v = 0; v < NPK; v++) {
        __half2 t = u2h(pk[v]);
        #pragma unroll
        for (int o = 16; o >= 2; o >>= 1)
            t = __hadd2(t, u2h(__shfl_xor_sync(0xffffffffu, h2u(t), o)));
        if (lane < 2) red[wrp][lane][v] = h2u(t);
    }
    __syncthreads();

    // ---- 24 finisher threads: fp32 sum of 16 packed rows + scalar math.
    if (tid < S * NC) {
        const int s = tid / NC;
        const int j = tid % NC;
        const int pss = s >> 1, sel = s & 1;
        const int pdd = 2 + j * 2 + (s >> 1);
        float ss = 0.f, dd = 0.f;
        #pragma unroll
        for (int w = 0; w < NW; w++) {
            #pragma unroll
            for (int ln = 0; ln < 2; ln++) {
                ss += unpack_sel(red[w][ln][pss], sel);
                dd += unpack_sel(red[w][ln][pdd], sel);
            }
        }
        const float inv = rsqrtf(ss * (1.0f / DIM) + 1.1920929e-7f);
        const float gv = tanhf(dd * inv);
        if (j < 5) coef[s * 5 + j] = fmaf(gv, *alpha_scale_p, static_alpha[s * 5 + j]);
        else       coef[20 + s]    = fmaf(gv, *beta_scale_p,  static_beta[s]);
    }
    __syncthreads();

    // ---- Mix in fp32 from fp16 x: out_t = sum_s gamma[t][s] * x_s,
    //      gamma[t][s] = alpha[s][t+1] + beta[t] * alpha[s][0].
    float xf[S][8];
    #pragma unroll
    for (int s = 0; s < S; s++) {
        #pragma unroll
        for (int k = 0; k < 4; k++) {
            float2 p = __half22float2(xh[s][k]);
            xf[s][2 * k]     = p.x;
            xf[s][2 * k + 1] = p.y;
        }
    }
    #pragma unroll
    for (int t = 0; t < S; t++) {
        const float bt = coef[20 + t];
        float gam[S];
        #pragma unroll
        for (int s = 0; s < S; s++) gam[s] = fmaf(bt, coef[s * 5], coef[s * 5 + t + 1]);
        float o[8];
        #pragma unroll
        for (int e = 0; e < 8; e++) {
            float r = gam[0] * xf[0][e];
            #pragma unroll
            for (int s = 1; s < S; s++) r = fmaf(gam[s], xf[s][e], r);
            o[e] = r;
        }
        float* po = out + base + (long long)t * SSTRIDE;
        __stcs(reinterpret_cast<float4*>(po + d0), make_float4(o[0], o[1], o[2], o[3]));
        __stcs(reinterpret_cast<float4*>(po + d1), make_float4(o[4], o[5], o[6], o[7]));
    }
}

}  // namespace

extern "C" void kernel_launch(void* const* d_in, const int* in_sizes, int n_in,
                              void* d_out, int out_size) {
    const float* residuals    = (const float*)d_in[0];
    const float* norm_weight  = (const float*)d_in[1];
    const float* static_alpha = (const float*)d_in[2];
    const float* static_beta  = (const float*)d_in[3];
    const float* alpha_fn     = (const float*)d_in[4];
    const float* alpha_scale  = (const float*)d_in[5];
    const float* beta_fn      = (const float*)d_in[6];
    const float* beta_scale   = (const float*)d_in[7];
    float* out = (float*)d_out;

    prep_kernel<<<(NC * DIM + 255) / 256, 256>>>(norm_weight, alpha_fn, beta_fn);

    // PDL launch: hyper begins launching while prep drains; the in-kernel
    // griddepcontrol.wait (after the x-loads) provides ordering.
    cudaLaunchConfig_t cfg = {};
    cfg.gridDim = dim3(4 * 2048);
    cfg.blockDim = dim3(TPB);
    cfg.dynamicSmemBytes = 0;
    cfg.stream = 0;
    cudaLaunchAttribute attrs[1];
    attrs[0].id = cudaLaunchAttributeProgrammaticStreamSerialization;
    attrs[0].val.programmaticStreamSerializationAllowed = 1;
    cfg.attrs = attrs;
    cfg.numAttrs = 1;
    cudaLaunchKernelEx(&cfg, hyper_kernel, residuals, static_alpha, static_beta,
                       alpha_scale, beta_scale, out);
}